// round 4
// baseline (speedup 1.0000x reference)
#include <cuda_runtime.h>

// Problem constants
#define TOK  16384
#define CMP  8192
#define HID  2048
#define ITR  8192

// GEMM tiling
#define BM 128
#define BN 64
#define BK 32

// 256MB scratch for h (silu(gate), then silu(gate)*up), 64MB for down-compact.
__device__ float g_h[(size_t)CMP * ITR];
__device__ float g_dc[(size_t)CMP * HID];

__device__ __forceinline__ unsigned f2tf32(float x) {
    unsigned r;
    asm("cvt.rna.tf32.f32 %0, %1;" : "=r"(r) : "f"(x));
    return r;
}

__device__ __forceinline__ float silu_f(float x) {
    return x / (1.0f + __expf(-x));
}

// XOR swizzle: place element (row k, col m) of the K-major smem tile at
// column m ^ (((k&3) ^ ((k>>2)&3)) << 3). Conflict-free fragment loads,
// <=2-way store conflicts, no padding (keeps static smem at exactly 48KB).
__device__ __forceinline__ int swz(int m, int k) {
    return m ^ ((((k) & 3) ^ (((k) >> 2) & 3)) << 3);
}

// C[M,N] = epilogue( A[M,K] @ B[N,K]^T )
// A rows optionally gathered through arow (fold_gather).
// MODE 0: silu(acc)     MODE 1: acc * aux[out_idx]     MODE 2: acc
template <int MODE>
__global__ __launch_bounds__(256, 2)
void gemm_tf32(const float* __restrict__ A, const float* __restrict__ B,
               float* __restrict__ C, const float* __restrict__ aux,
               const int* __restrict__ arow, int M, int N, int K)
{
    __shared__ unsigned sA[2][BK][BM];   // 32KB
    __shared__ unsigned sB[2][BK][BN];   // 16KB  -> 48KB total

    const int tid  = threadIdx.x;
    const int lane = tid & 31;
    const int warp = tid >> 5;
    const int gid  = lane >> 2;     // 0..7
    const int tig  = lane & 3;      // 0..3
    const int wm   = (warp & 3) * 32;
    const int wn   = (warp >> 2) * 32;
    const int m0   = blockIdx.y * BM;
    const int n0   = blockIdx.x * BN;

    // Global tile load assignment: 8 lanes per row, float4 along K.
    const int rA = tid >> 3;          // 0..31
    const int kq = (tid & 7) * 4;     // 0,4,...,28

    const float* aptr[4];
    #pragma unroll
    for (int i = 0; i < 4; i++) {
        int gr  = m0 + rA + 32 * i;
        int row = arow ? __ldg(arow + gr) : gr;
        aptr[i] = A + (size_t)row * K + kq;
    }
    const float* bptr[2];
    #pragma unroll
    for (int i = 0; i < 2; i++)
        bptr[i] = B + (size_t)(n0 + rA + 32 * i) * K + kq;

    float4 ra[4], rb[2];
    #pragma unroll
    for (int i = 0; i < 4; i++) ra[i] = *(const float4*)aptr[i];
    #pragma unroll
    for (int i = 0; i < 2; i++) rb[i] = *(const float4*)bptr[i];

    float acc[2][4][4];
    #pragma unroll
    for (int mi = 0; mi < 2; mi++)
        #pragma unroll
        for (int ni = 0; ni < 4; ni++)
            #pragma unroll
            for (int j = 0; j < 4; j++) acc[mi][ni][j] = 0.0f;

    auto store_tile = [&](int b) {
        #pragma unroll
        for (int i = 0; i < 4; i++) {
            int r = rA + 32 * i;
            const float* v = (const float*)&ra[i];
            #pragma unroll
            for (int j = 0; j < 4; j++) {
                int k = kq + j;
                sA[b][k][swz(r, k)] = f2tf32(v[j]);
            }
        }
        #pragma unroll
        for (int i = 0; i < 2; i++) {
            int r = rA + 32 * i;
            const float* v = (const float*)&rb[i];
            #pragma unroll
            for (int j = 0; j < 4; j++) {
                int k = kq + j;
                sB[b][k][swz(r, k)] = f2tf32(v[j]);
            }
        }
    };

    int buf = 0;
    store_tile(0);
    __syncthreads();

    const int KT = K / BK;
    for (int kt = 0; kt < KT; kt++) {
        if (kt + 1 < KT) {
            int off = (kt + 1) * BK;
            #pragma unroll
            for (int i = 0; i < 4; i++) ra[i] = *(const float4*)(aptr[i] + off);
            #pragma unroll
            for (int i = 0; i < 2; i++) rb[i] = *(const float4*)(bptr[i] + off);
        }

        #pragma unroll
        for (int ks = 0; ks < 4; ks++) {
            const int k0 = ks * 8 + tig;      // rows for a0/a1/b0
            const int k1 = k0 + 4;            // rows for a2/a3/b1
            const int s0 = (((k0) & 3) ^ (((k0) >> 2) & 3)) << 3;
            const int s1 = (((k1) & 3) ^ (((k1) >> 2) & 3)) << 3;

            unsigned afr[2][4], bfr[4][2];
            #pragma unroll
            for (int mi = 0; mi < 2; mi++) {
                int m = wm + mi * 16 + gid;
                afr[mi][0] = sA[buf][k0][m ^ s0];
                afr[mi][1] = sA[buf][k0][(m + 8) ^ s0];
                afr[mi][2] = sA[buf][k1][m ^ s1];
                afr[mi][3] = sA[buf][k1][(m + 8) ^ s1];
            }
            #pragma unroll
            for (int ni = 0; ni < 4; ni++) {
                int n = wn + ni * 8 + gid;
                bfr[ni][0] = sB[buf][k0][n ^ s0];
                bfr[ni][1] = sB[buf][k1][n ^ s1];
            }
            #pragma unroll
            for (int mi = 0; mi < 2; mi++)
                #pragma unroll
                for (int ni = 0; ni < 4; ni++)
                    asm volatile(
                        "mma.sync.aligned.m16n8k8.row.col.f32.tf32.tf32.f32 "
                        "{%0,%1,%2,%3}, {%4,%5,%6,%7}, {%8,%9}, {%0,%1,%2,%3};\n"
                        : "+f"(acc[mi][ni][0]), "+f"(acc[mi][ni][1]),
                          "+f"(acc[mi][ni][2]), "+f"(acc[mi][ni][3])
                        : "r"(afr[mi][0]), "r"(afr[mi][1]),
                          "r"(afr[mi][2]), "r"(afr[mi][3]),
                          "r"(bfr[ni][0]), "r"(bfr[ni][1]));
        }

        if (kt + 1 < KT) {
            store_tile(buf ^ 1);
            __syncthreads();
            buf ^= 1;
        }
    }

    // Epilogue: c0,c1 at (row, col..col+1), c2,c3 at (row+8, col..col+1)
    #pragma unroll
    for (int mi = 0; mi < 2; mi++) {
        #pragma unroll
        for (int ni = 0; ni < 4; ni++) {
            int row = m0 + wm + mi * 16 + gid;
            int col = n0 + wn + ni * 8 + tig * 2;
            size_t i0 = (size_t)row * N + col;
            size_t i1 = i0 + (size_t)8 * N;
            float2 v0 = make_float2(acc[mi][ni][0], acc[mi][ni][1]);
            float2 v1 = make_float2(acc[mi][ni][2], acc[mi][ni][3]);
            if (MODE == 0) {
                v0.x = silu_f(v0.x); v0.y = silu_f(v0.y);
                v1.x = silu_f(v1.x); v1.y = silu_f(v1.y);
            } else if (MODE == 1) {
                float2 a0 = *(const float2*)(aux + i0);
                float2 a1 = *(const float2*)(aux + i1);
                v0.x *= a0.x; v0.y *= a0.y;
                v1.x *= a1.x; v1.y *= a1.y;
            }
            *(float2*)(C + i0) = v0;
            *(float2*)(C + i1) = v1;
        }
    }
}

// out[n, :] = dc[scatter_indices[n], :]
__global__ void scatter_rows(const float* __restrict__ dc,
                             const int* __restrict__ sc,
                             float* __restrict__ out)
{
    int n = blockIdx.x;
    int c = __ldg(sc + n);
    const float4* s = (const float4*)(dc + (size_t)c * HID);
    float4*       d = (float4*)(out + (size_t)n * HID);
    #pragma unroll
    for (int j = threadIdx.x; j < HID / 4; j += 256)
        d[j] = s[j];
}

extern "C" void kernel_launch(void* const* d_in, const int* in_sizes, int n_in,
                              void* d_out, int out_size)
{
    (void)in_sizes; (void)n_in; (void)out_size;
    const float* x  = (const float*)d_in[0];   // [16384, 2048]
    const float* Wg = (const float*)d_in[1];   // [8192, 2048]
    const float* Wu = (const float*)d_in[2];   // [8192, 2048]
    const float* Wd = (const float*)d_in[3];   // [2048, 8192]
    const int*   fg = (const int*)d_in[4];     // [8192]
    const int*   sc = (const int*)d_in[5];     // [16384]
    float* out = (float*)d_out;                // [16384, 2048]

    float *h = nullptr, *dc = nullptr;
    cudaGetSymbolAddress((void**)&h,  g_h);
    cudaGetSymbolAddress((void**)&dc, g_dc);

    dim3 blk(256);
    dim3 g1(ITR / BN, CMP / BM);   // 128 x 64
    dim3 g2(HID / BN, CMP / BM);   //  32 x 64

    // h = silu(gather(x) @ Wg^T)
    gemm_tf32<0><<<g1, blk>>>(x, Wg, h, nullptr, fg, CMP, ITR, HID);
    // h = (gather(x) @ Wu^T) * h
    gemm_tf32<1><<<g1, blk>>>(x, Wu, h, h, fg, CMP, ITR, HID);
    // dc = h @ Wd^T
    gemm_tf32<2><<<g2, blk>>>(h, Wd, dc, nullptr, nullptr, CMP, HID, ITR);
    // out = dc[sc]
    scatter_rows<<<TOK, 256>>>(dc, sc, out);
}

// round 8
// speedup vs baseline: 1.7713x; 1.7713x over previous
#include <cuda_runtime.h>
#include <cstdint>

#define TOK 16384
#define CMP 8192
#define HID 2048
#define ITR 8192

#define NST 3            // cp.async pipeline depth
#define BM 128
#define BN 64
#define BK 32            // 128 bytes per row per tile

// tf32-rounded operand scratch + intermediates
__device__ float g_xg[(size_t)CMP * HID];
__device__ float g_wg[(size_t)ITR * HID];
__device__ float g_wu[(size_t)ITR * HID];
__device__ float g_wd[(size_t)HID * ITR];
__device__ float g_h [(size_t)CMP * ITR];
__device__ float g_dc[(size_t)CMP * HID];

// ---------------------------------------------------------------- helpers
static __device__ __forceinline__ unsigned f2tf32(float x){
    unsigned r; asm("cvt.rna.tf32.f32 %0, %1;" : "=r"(r) : "f"(x)); return r;
}
static __device__ __forceinline__ float silu_f(float x){ return x / (1.0f + __expf(-x)); }

static __device__ __forceinline__ uint32_t s2u(const void* p){
    uint32_t a;
    asm("{ .reg .u64 t; cvta.to.shared.u64 t, %1; cvt.u32.u64 %0, t; }" : "=r"(a) : "l"(p));
    return a;
}
static __device__ __forceinline__ void cp16(uint32_t dst, const void* src){
    asm volatile("cp.async.cg.shared.global [%0], [%1], 16;" :: "r"(dst), "l"(src));
}
static __device__ __forceinline__ void cp_commit(){
    asm volatile("cp.async.commit_group;" ::: "memory");
}
static __device__ __forceinline__ void cp_wait1(){
    asm volatile("cp.async.wait_group 1;" ::: "memory");
}

// word index of element (row r, k) inside a [rows][32]-float tile whose 16B
// chunks are XOR-swizzled: chunk j at j ^ (r & 7). Conflict-free for both the
// cp.async stores and the mma fragment LDS patterns.
static __device__ __forceinline__ int widx(int r, int k){
    return r * 32 + (k & 3) + ((((k >> 2) ^ r) & 7) << 2);
}

static __device__ __forceinline__ void mma_tf32(float* d, const unsigned* a,
                                                const unsigned* b){
    asm volatile(
        "mma.sync.aligned.m16n8k8.row.col.f32.tf32.tf32.f32 "
        "{%0,%1,%2,%3}, {%4,%5,%6,%7}, {%8,%9}, {%0,%1,%2,%3};\n"
        : "+f"(d[0]), "+f"(d[1]), "+f"(d[2]), "+f"(d[3])
        : "r"(a[0]), "r"(a[1]), "r"(a[2]), "r"(a[3]), "r"(b[0]), "r"(b[1]));
}

// ---------------------------------------------------------------- GEMM
// C[M,N] = A[M,K] @ B^T  (A,B K-major, pre-rounded tf32 bit patterns).
// FUSED=1: two B matrices (gate/up); epilogue C = tf32(silu(g) * u).
// FUSED=0: single B; plain fp32 store.
// Block tile 128x64, 8 warps as 4(m) x 2(n), warp tile 32x32 per B.
template<int FUSED>
__global__ void __launch_bounds__(256, 2)
gemm_mma(const float* __restrict__ A, const float* __restrict__ B0,
         const float* __restrict__ B1, float* __restrict__ C, int N, int K)
{
    extern __shared__ float smem[];
    constexpr int SA  = BM * BK;                    // 4096 floats
    constexpr int SB  = BN * BK;                    // 2048 floats
    constexpr int STG = SA + SB * (FUSED ? 2 : 1);  // floats per stage

    const int tid  = threadIdx.x;
    const int lane = tid & 31;
    const int warp = tid >> 5;
    const int gid  = lane >> 2;          // 0..7
    const int tig  = lane & 3;           // 0..3
    const int wm   = (warp & 3) * 32;
    const int wn   = (warp >> 2) * 32;
    const int m0   = blockIdx.y * BM;
    const int n0   = blockIdx.x * BN;
    const int KT   = K / BK;

    // producer assignment: 8 chunks (16B) per 128B row
    const int lrow = tid >> 3;           // 0..31
    const int lj   = tid & 7;            // chunk 0..7
    const uint32_t sbase = s2u(smem);

    const float* Ap  = A  + (size_t)(m0 + lrow) * K + lj * 4;
    const float* B0p = B0 + (size_t)(n0 + lrow) * K + lj * 4;
    const float* B1p = FUSED ? (B1 + (size_t)(n0 + lrow) * K + lj * 4) : B0;

    auto load_stage = [&](int st, int kt){
        const uint32_t tb = sbase + (uint32_t)st * STG * 4;
        const size_t go = (size_t)kt * BK;
        #pragma unroll
        for (int i = 0; i < 4; i++) {
            const int r = lrow + 32 * i;
            const uint32_t off = (uint32_t)(r * 32 + ((lj ^ (r & 7)) << 2)) * 4;
            cp16(tb + off, Ap + (size_t)(32 * i) * K + go);
        }
        #pragma unroll
        for (int i = 0; i < 2; i++) {
            const int r = lrow + 32 * i;
            const uint32_t off = (uint32_t)(r * 32 + ((lj ^ (r & 7)) << 2)) * 4;
            cp16(tb + SA * 4 + off, B0p + (size_t)(32 * i) * K + go);
            if (FUSED)
                cp16(tb + (SA + SB) * 4 + off, B1p + (size_t)(32 * i) * K + go);
        }
        cp_commit();
    };

    float accG[2][4][4];
    float accU[2][4][4];
    #pragma unroll
    for (int mi = 0; mi < 2; mi++)
        #pragma unroll
        for (int nf = 0; nf < 4; nf++)
            #pragma unroll
            for (int j = 0; j < 4; j++) {
                accG[mi][nf][j] = 0.0f;
                if (FUSED) accU[mi][nf][j] = 0.0f;
            }

    // prologue: fill NST-1 stages
    #pragma unroll
    for (int s = 0; s < NST - 1; s++) load_stage(s, s);

    for (int kt = 0; kt < KT; kt++) {
        cp_wait1();
        __syncthreads();

        const int nxt = kt + NST - 1;
        if (nxt < KT) load_stage(nxt % NST, nxt);
        else          cp_commit();          // keep group count uniform

        const unsigned* sA = (const unsigned*)(smem + (kt % NST) * STG);
        const unsigned* sG = sA + SA;
        const unsigned* sU = sG + SB;

        #pragma unroll
        for (int ks = 0; ks < 4; ks++) {
            const int ka = ks * 8 + tig;     // k for a0/a1/b0
            const int kb = ka + 4;           // k for a2/a3/b1

            unsigned af[2][4];
            #pragma unroll
            for (int mi = 0; mi < 2; mi++) {
                const int m = wm + mi * 16 + gid;
                af[mi][0] = sA[widx(m,     ka)];
                af[mi][1] = sA[widx(m + 8, ka)];
                af[mi][2] = sA[widx(m,     kb)];
                af[mi][3] = sA[widx(m + 8, kb)];
            }
            unsigned bg[4][2], bu[4][2];
            #pragma unroll
            for (int nf = 0; nf < 4; nf++) {
                const int n = wn + nf * 8 + gid;
                bg[nf][0] = sG[widx(n, ka)];
                bg[nf][1] = sG[widx(n, kb)];
                if (FUSED) {
                    bu[nf][0] = sU[widx(n, ka)];
                    bu[nf][1] = sU[widx(n, kb)];
                }
            }
            #pragma unroll
            for (int mi = 0; mi < 2; mi++)
                #pragma unroll
                for (int nf = 0; nf < 4; nf++) {
                    mma_tf32(accG[mi][nf], af[mi], bg[nf]);
                    if (FUSED) mma_tf32(accU[mi][nf], af[mi], bu[nf]);
                }
        }
    }

    // ---------------- epilogue
    #pragma unroll
    for (int mi = 0; mi < 2; mi++) {
        #pragma unroll
        for (int nf = 0; nf < 4; nf++) {
            const int row = m0 + wm + mi * 16 + gid;
            const int col = n0 + wn + nf * 8 + tig * 2;
            const size_t i0 = (size_t)row * N + col;
            const size_t i1 = i0 + (size_t)8 * N;
            if (FUSED) {
                float y0 = silu_f(accG[mi][nf][0]) * accU[mi][nf][0];
                float y1 = silu_f(accG[mi][nf][1]) * accU[mi][nf][1];
                float y2 = silu_f(accG[mi][nf][2]) * accU[mi][nf][2];
                float y3 = silu_f(accG[mi][nf][3]) * accU[mi][nf][3];
                uint2 v0 = { f2tf32(y0), f2tf32(y1) };
                uint2 v1 = { f2tf32(y2), f2tf32(y3) };
                *(uint2*)(C + i0) = v0;
                *(uint2*)(C + i1) = v1;
            } else {
                float2 v0 = make_float2(accG[mi][nf][0], accG[mi][nf][1]);
                float2 v1 = make_float2(accG[mi][nf][2], accG[mi][nf][3]);
                *(float2*)(C + i0) = v0;
                *(float2*)(C + i1) = v1;
            }
        }
    }
}

// ---------------------------------------------------------------- prep + scatter
__global__ void conv_tf32(const float* __restrict__ in, float* __restrict__ out, size_t n){
    size_t i = (size_t)blockIdx.x * blockDim.x + threadIdx.x;
    const size_t stride = (size_t)gridDim.x * blockDim.x;
    for (; i < n / 4; i += stride) {
        float4 v = ((const float4*)in)[i];
        uint4 o = { f2tf32(v.x), f2tf32(v.y), f2tf32(v.z), f2tf32(v.w) };
        ((uint4*)out)[i] = o;
    }
}

__global__ void gather_conv(const float* __restrict__ x, const int* __restrict__ fg,
                            float* __restrict__ out){
    const int c = blockIdx.x;
    const int src = __ldg(fg + c);
    const float4* s = (const float4*)(x + (size_t)src * HID);
    uint4* d = (uint4*)(out + (size_t)c * HID);
    for (int j = threadIdx.x; j < HID / 4; j += blockDim.x) {
        float4 v = s[j];
        uint4 o = { f2tf32(v.x), f2tf32(v.y), f2tf32(v.z), f2tf32(v.w) };
        d[j] = o;
    }
}

__global__ void scatter_rows(const float* __restrict__ dc, const int* __restrict__ sc,
                             float* __restrict__ out){
    const int n = blockIdx.x;
    const int c = __ldg(sc + n);
    const float4* s = (const float4*)(dc + (size_t)c * HID);
    float4* d = (float4*)(out + (size_t)n * HID);
    #pragma unroll
    for (int j = threadIdx.x; j < HID / 4; j += 256)
        d[j] = s[j];
}

// ---------------------------------------------------------------- launch
extern "C" void kernel_launch(void* const* d_in, const int* in_sizes, int n_in,
                              void* d_out, int out_size)
{
    (void)in_sizes; (void)n_in; (void)out_size;
    const float* x  = (const float*)d_in[0];   // [16384, 2048]
    const float* Wg = (const float*)d_in[1];   // [8192, 2048]
    const float* Wu = (const float*)d_in[2];   // [8192, 2048]
    const float* Wd = (const float*)d_in[3];   // [2048, 8192]
    const int*   fg = (const int*)d_in[4];     // [8192]
    const int*   sc = (const int*)d_in[5];     // [16384]
    float* out = (float*)d_out;                // [16384, 2048]

    float *xg, *wg, *wu, *wd, *h, *dc;
    cudaGetSymbolAddress((void**)&xg, g_xg);
    cudaGetSymbolAddress((void**)&wg, g_wg);
    cudaGetSymbolAddress((void**)&wu, g_wu);
    cudaGetSymbolAddress((void**)&wd, g_wd);
    cudaGetSymbolAddress((void**)&h,  g_h);
    cudaGetSymbolAddress((void**)&dc, g_dc);

    const int SMEM_F = NST * (BM * BK + 2 * BN * BK) * 4;   // 98304
    const int SMEM_P = NST * (BM * BK + 1 * BN * BK) * 4;   // 73728
    cudaFuncSetAttribute(gemm_mma<1>, cudaFuncAttributeMaxDynamicSharedMemorySize, SMEM_F);
    cudaFuncSetAttribute(gemm_mma<0>, cudaFuncAttributeMaxDynamicSharedMemorySize, SMEM_P);

    // RNA-round operands to tf32 bit patterns (gather folded into x pass)
    gather_conv<<<CMP, 256>>>(x, fg, xg);
    conv_tf32<<<4096, 256>>>(Wg, wg, (size_t)ITR * HID);
    conv_tf32<<<4096, 256>>>(Wu, wu, (size_t)ITR * HID);
    conv_tf32<<<4096, 256>>>(Wd, wd, (size_t)HID * ITR);

    // h = tf32( silu(xg @ Wg^T) * (xg @ Wu^T) )   [fused dual-accumulator]
    gemm_mma<1><<<dim3(ITR / BN, CMP / BM), 256, SMEM_F>>>(xg, wg, wu, h, ITR, HID);
    // dc = h @ Wd^T
    gemm_mma<0><<<dim3(HID / BN, CMP / BM), 256, SMEM_P>>>(h, wd, nullptr, dc, HID, ITR);
    // out = dc[sc]
    scatter_rows<<<TOK, 256>>>(dc, sc, out);
}

// round 9
// speedup vs baseline: 3.4576x; 1.9520x over previous
#include <cuda_runtime.h>
#include <cuda_fp16.h>
#include <cstdint>

#define TOK 16384
#define CMP 8192
#define HID 2048
#define ITR 8192

#define NST 3            // cp.async pipeline depth
#define BM 128
#define BN 64
#define BK 64            // fp16 elements per K-chunk = 128 bytes per row

// fp16 operand scratch + intermediates
__device__ __half g_xg[(size_t)CMP * HID];
__device__ __half g_wg[(size_t)ITR * HID];
__device__ __half g_wu[(size_t)ITR * HID];
__device__ __half g_wd[(size_t)HID * ITR];
__device__ __half g_h [(size_t)CMP * ITR];
__device__ float  g_dc[(size_t)CMP * HID];

// ---------------------------------------------------------------- helpers
static __device__ __forceinline__ float silu_f(float x){ return x / (1.0f + __expf(-x)); }

static __device__ __forceinline__ uint32_t s2u(const void* p){
    uint32_t a;
    asm("{ .reg .u64 t; cvta.to.shared.u64 t, %1; cvt.u32.u64 %0, t; }" : "=r"(a) : "l"(p));
    return a;
}
static __device__ __forceinline__ void cp16(uint32_t dst, const void* src){
    asm volatile("cp.async.cg.shared.global [%0], [%1], 16;" :: "r"(dst), "l"(src));
}
static __device__ __forceinline__ void cp_commit(){
    asm volatile("cp.async.commit_group;" ::: "memory");
}
static __device__ __forceinline__ void cp_wait1(){
    asm volatile("cp.async.wait_group 1;" ::: "memory");
}

// 32-bit-word index (f16x2 granularity) of element (row r, k) in a
// [rows][64-half] tile whose 16B chunks are XOR-swizzled: chunk j -> j ^ (r&7).
// k must be even. Conflict-free for cp.async stores and mma fragment loads.
static __device__ __forceinline__ int hidx(int r, int k){
    return r * 32 + ((((k >> 3) ^ r) & 7) << 2) + ((k >> 1) & 3);
}

static __device__ __forceinline__ void mma_f16(float* d, const unsigned* a,
                                               const unsigned* b){
    asm volatile(
        "mma.sync.aligned.m16n8k16.row.col.f32.f16.f16.f32 "
        "{%0,%1,%2,%3}, {%4,%5,%6,%7}, {%8,%9}, {%0,%1,%2,%3};\n"
        : "+f"(d[0]), "+f"(d[1]), "+f"(d[2]), "+f"(d[3])
        : "r"(a[0]), "r"(a[1]), "r"(a[2]), "r"(a[3]), "r"(b[0]), "r"(b[1]));
}

// ---------------------------------------------------------------- GEMM
// C = A[M,K] @ B^T   (A,B fp16 K-major; fp32 accumulate).
// FUSED=1: two B matrices (gate/up); epilogue C = half(silu(g) * u).
// FUSED=0: single B; fp32 store.
// Block tile 128x64, 8 warps as 4(m) x 2(n), warp tile 32x32 per B.
template<int FUSED>
__global__ void __launch_bounds__(256, 2)
gemm_mma(const __half* __restrict__ A, const __half* __restrict__ B0,
         const __half* __restrict__ B1, void* __restrict__ Cv, int N, int K)
{
    extern __shared__ char smem[];
    constexpr int SAB = BM * BK * 2;                      // 16384 B
    constexpr int SBB = BN * BK * 2;                      //  8192 B
    constexpr int STG = SAB + SBB * (FUSED ? 2 : 1);      // bytes per stage

    const int tid  = threadIdx.x;
    const int lane = tid & 31;
    const int warp = tid >> 5;
    const int gid  = lane >> 2;          // 0..7
    const int tig  = lane & 3;           // 0..3
    const int wm   = (warp & 3) * 32;
    const int wn   = (warp >> 2) * 32;
    const int m0   = blockIdx.y * BM;
    const int n0   = blockIdx.x * BN;
    const int KT   = K / BK;

    // producer assignment: 8 chunks (16B = 8 halves) per 128B row
    const int lrow = tid >> 3;           // 0..31
    const int lj   = tid & 7;            // chunk 0..7
    const uint32_t sbase = s2u(smem);

    const __half* Ap  = A  + (size_t)(m0 + lrow) * K + lj * 8;
    const __half* B0p = B0 + (size_t)(n0 + lrow) * K + lj * 8;
    const __half* B1p = FUSED ? (B1 + (size_t)(n0 + lrow) * K + lj * 8) : B0;

    auto load_stage = [&](int st, int kt){
        const uint32_t tb = sbase + (uint32_t)st * STG;
        const size_t go = (size_t)kt * BK;
        #pragma unroll
        for (int i = 0; i < 4; i++) {
            const int r = lrow + 32 * i;
            const uint32_t off = (uint32_t)(r * 128 + ((lj ^ (r & 7)) << 4));
            cp16(tb + off, Ap + (size_t)(32 * i) * K + go);
        }
        #pragma unroll
        for (int i = 0; i < 2; i++) {
            const int r = lrow + 32 * i;
            const uint32_t off = (uint32_t)(r * 128 + ((lj ^ (r & 7)) << 4));
            cp16(tb + SAB + off, B0p + (size_t)(32 * i) * K + go);
            if (FUSED)
                cp16(tb + SAB + SBB + off, B1p + (size_t)(32 * i) * K + go);
        }
        cp_commit();
    };

    float accG[2][4][4];
    float accU[2][4][4];
    #pragma unroll
    for (int mi = 0; mi < 2; mi++)
        #pragma unroll
        for (int nf = 0; nf < 4; nf++)
            #pragma unroll
            for (int j = 0; j < 4; j++) {
                accG[mi][nf][j] = 0.0f;
                if (FUSED) accU[mi][nf][j] = 0.0f;
            }

    // prologue: fill NST-1 stages
    #pragma unroll
    for (int s = 0; s < NST - 1; s++) load_stage(s, s);

    for (int kt = 0; kt < KT; kt++) {
        cp_wait1();
        __syncthreads();

        const int nxt = kt + NST - 1;
        if (nxt < KT) load_stage(nxt % NST, nxt);
        else          cp_commit();          // keep group count uniform

        const unsigned* sA = (const unsigned*)(smem + (kt % NST) * STG);
        const unsigned* sG = (const unsigned*)(smem + (kt % NST) * STG + SAB);
        const unsigned* sU = (const unsigned*)(smem + (kt % NST) * STG + SAB + SBB);

        #pragma unroll
        for (int ks = 0; ks < 4; ks++) {
            const int kk = ks * 16 + 2 * tig;     // even k for f16x2 loads

            unsigned af[2][4];
            #pragma unroll
            for (int mi = 0; mi < 2; mi++) {
                const int m = wm + mi * 16 + gid;
                af[mi][0] = sA[hidx(m,     kk)];
                af[mi][1] = sA[hidx(m + 8, kk)];
                af[mi][2] = sA[hidx(m,     kk + 8)];
                af[mi][3] = sA[hidx(m + 8, kk + 8)];
            }
            unsigned bg[4][2], bu[4][2];
            #pragma unroll
            for (int nf = 0; nf < 4; nf++) {
                const int n = wn + nf * 8 + gid;
                bg[nf][0] = sG[hidx(n, kk)];
                bg[nf][1] = sG[hidx(n, kk + 8)];
                if (FUSED) {
                    bu[nf][0] = sU[hidx(n, kk)];
                    bu[nf][1] = sU[hidx(n, kk + 8)];
                }
            }
            #pragma unroll
            for (int mi = 0; mi < 2; mi++)
                #pragma unroll
                for (int nf = 0; nf < 4; nf++) {
                    mma_f16(accG[mi][nf], af[mi], bg[nf]);
                    if (FUSED) mma_f16(accU[mi][nf], af[mi], bu[nf]);
                }
        }
    }

    // ---------------- epilogue
    #pragma unroll
    for (int mi = 0; mi < 2; mi++) {
        #pragma unroll
        for (int nf = 0; nf < 4; nf++) {
            const int row = m0 + wm + mi * 16 + gid;
            const int col = n0 + wn + nf * 8 + tig * 2;
            const size_t i0 = (size_t)row * N + col;
            const size_t i1 = i0 + (size_t)8 * N;
            if (FUSED) {
                __half* C = (__half*)Cv;
                __half2 v0 = __floats2half2_rn(
                    silu_f(accG[mi][nf][0]) * accU[mi][nf][0],
                    silu_f(accG[mi][nf][1]) * accU[mi][nf][1]);
                __half2 v1 = __floats2half2_rn(
                    silu_f(accG[mi][nf][2]) * accU[mi][nf][2],
                    silu_f(accG[mi][nf][3]) * accU[mi][nf][3]);
                *(__half2*)(C + i0) = v0;
                *(__half2*)(C + i1) = v1;
            } else {
                float* C = (float*)Cv;
                float2 v0 = make_float2(accG[mi][nf][0], accG[mi][nf][1]);
                float2 v1 = make_float2(accG[mi][nf][2], accG[mi][nf][3]);
                *(float2*)(C + i0) = v0;
                *(float2*)(C + i1) = v1;
            }
        }
    }
}

// ---------------------------------------------------------------- prep + scatter
__global__ void conv_h(const float* __restrict__ in, __half* __restrict__ out, size_t n){
    size_t i = (size_t)blockIdx.x * blockDim.x + threadIdx.x;
    const size_t stride = (size_t)gridDim.x * blockDim.x;
    for (; i < n / 4; i += stride) {
        float4 v = ((const float4*)in)[i];
        __half2 lo = __floats2half2_rn(v.x, v.y);
        __half2 hi = __floats2half2_rn(v.z, v.w);
        ((__half2*)out)[i * 2]     = lo;
        ((__half2*)out)[i * 2 + 1] = hi;
    }
}

__global__ void gather_conv_h(const float* __restrict__ x, const int* __restrict__ fg,
                              __half* __restrict__ out){
    const int c = blockIdx.x;
    const int src = __ldg(fg + c);
    const float4* s = (const float4*)(x + (size_t)src * HID);
    __half2* d = (__half2*)(out + (size_t)c * HID);
    for (int j = threadIdx.x; j < HID / 4; j += blockDim.x) {
        float4 v = s[j];
        d[j * 2]     = __floats2half2_rn(v.x, v.y);
        d[j * 2 + 1] = __floats2half2_rn(v.z, v.w);
    }
}

__global__ void scatter_rows(const float* __restrict__ dc, const int* __restrict__ sc,
                             float* __restrict__ out){
    const int n = blockIdx.x;
    const int c = __ldg(sc + n);
    const float4* s = (const float4*)(dc + (size_t)c * HID);
    float4* d = (float4*)(out + (size_t)n * HID);
    #pragma unroll
    for (int j = threadIdx.x; j < HID / 4; j += 256)
        d[j] = s[j];
}

// ---------------------------------------------------------------- launch
extern "C" void kernel_launch(void* const* d_in, const int* in_sizes, int n_in,
                              void* d_out, int out_size)
{
    (void)in_sizes; (void)n_in; (void)out_size;
    const float* x  = (const float*)d_in[0];   // [16384, 2048]
    const float* Wg = (const float*)d_in[1];   // [8192, 2048]
    const float* Wu = (const float*)d_in[2];   // [8192, 2048]
    const float* Wd = (const float*)d_in[3];   // [2048, 8192]
    const int*   fg = (const int*)d_in[4];     // [8192]
    const int*   sc = (const int*)d_in[5];     // [16384]
    float* out = (float*)d_out;                // [16384, 2048]

    __half *xg, *wg, *wu, *wd, *h;
    float *dc;
    cudaGetSymbolAddress((void**)&xg, g_xg);
    cudaGetSymbolAddress((void**)&wg, g_wg);
    cudaGetSymbolAddress((void**)&wu, g_wu);
    cudaGetSymbolAddress((void**)&wd, g_wd);
    cudaGetSymbolAddress((void**)&h,  g_h);
    cudaGetSymbolAddress((void**)&dc, g_dc);

    const int SMEM_F = NST * (BM + 2 * BN) * BK * 2;   // 98304
    const int SMEM_P = NST * (BM + 1 * BN) * BK * 2;   // 73728
    cudaFuncSetAttribute(gemm_mma<1>, cudaFuncAttributeMaxDynamicSharedMemorySize, SMEM_F);
    cudaFuncSetAttribute(gemm_mma<0>, cudaFuncAttributeMaxDynamicSharedMemorySize, SMEM_P);

    // RN-round operands to fp16 (gather folded into x pass)
    gather_conv_h<<<CMP, 256>>>(x, fg, xg);
    conv_h<<<4096, 256>>>(Wg, wg, (size_t)ITR * HID);
    conv_h<<<4096, 256>>>(Wu, wu, (size_t)ITR * HID);
    conv_h<<<4096, 256>>>(Wd, wd, (size_t)HID * ITR);

    // h = half( silu(xg @ Wg^T) * (xg @ Wu^T) )   [fused dual-accumulator]
    gemm_mma<1><<<dim3(ITR / BN, CMP / BM), 256, SMEM_F>>>(xg, wg, wu, h, ITR, HID);
    // dc = h @ Wd^T
    gemm_mma<0><<<dim3(HID / BN, CMP / BM), 256, SMEM_P>>>(h, wd, nullptr, dc, HID, ITR);
    // out = dc[sc]
    scatter_rows<<<TOK, 256>>>(dc, sc, out);
}